// round 15
// baseline (speedup 1.0000x reference)
#include <cuda_runtime.h>
#include <cstdint>

#define NB 32
#define NH 512
#define NW 512
#define NHW (NH * NW)          // 262144
#define PARTS 64
#define CHUNK (NHW / PARTS)    // 4096
#define FOV 160.0f             // 0.3125 * 512
#define KCONST 106.496f        // 0.208  * 512

// scratch (no allocations allowed)
__device__ float g_part[NB * PARTS * 3];
__device__ float g_params[NB * 8];   // xg, yg, fe, coef | invden, addc

// --- PDL helpers -----------------------------------------------------------
__device__ __forceinline__ void pdl_wait() {
    asm volatile("griddepcontrol.wait;" ::: "memory");
}
__device__ __forceinline__ void pdl_launch_dependents() {
    asm volatile("griddepcontrol.launch_dependents;" ::: "memory");
}
__device__ __forceinline__ void prefetch_l2(const void* p) {
    asm volatile("prefetch.global.L2 [%0];" :: "l"(p));
}

// ---------------------------------------------------------------------------
// Kernel 1: per-(batch, part) partial sums of S, S*r, S*r^2
// grid = (PARTS, NB) = 2048 blocks x 256. 4 front-batched LDG.128 (MLP=4).
// ---------------------------------------------------------------------------
__global__ void __launch_bounds__(256, 8) sal_reduce_kernel(
    const float* __restrict__ sal, const float* __restrict__ gaze)
{
    const int b = blockIdx.y;
    const int p = blockIdx.x;
    const float xg = __ldg(&gaze[2 * b]);
    const float yg = __ldg(&gaze[2 * b + 1]);
    const float4* S4 = (const float4*)(sal + (size_t)b * NHW + (size_t)p * CHUNK);
    const int base_lin = p * CHUNK;

    // front-batch all 4 LDG.128s for memory-level parallelism
    float4 v[4];
    #pragma unroll
    for (int it = 0; it < 4; it++)
        v[it] = __ldg(&S4[it * 256 + threadIdx.x]);

    float s0 = 0.f, s1 = 0.f, s2 = 0.f;
    #pragma unroll
    for (int it = 0; it < 4; it++) {
        int lin = base_lin + (it * 256 + threadIdx.x) * 4;
        float dy = (float)(lin >> 9) - yg;
        float dy2 = fmaf(dy, dy, 1e-6f);
        int x0 = lin & 511;
        #pragma unroll
        for (int k = 0; k < 4; k++) {
            float dx = (float)(x0 + k) - xg;
            float d2 = fmaf(dx, dx, dy2);
            float r  = d2 * rsqrtf(d2);       // r = sqrt(d2), 1 MUFU
            float sv = (&v[it].x)[k];
            s0 += sv;
            s1 = fmaf(sv, r, s1);
            s2 = fmaf(sv, d2, s2);            // r^2 == d2 exactly
        }
    }

    // block reduction
    __shared__ float sh[3][8];
    #pragma unroll
    for (int off = 16; off; off >>= 1) {
        s0 += __shfl_down_sync(0xffffffffu, s0, off);
        s1 += __shfl_down_sync(0xffffffffu, s1, off);
        s2 += __shfl_down_sync(0xffffffffu, s2, off);
    }
    const int wid = threadIdx.x >> 5, lane = threadIdx.x & 31;
    if (lane == 0) { sh[0][wid] = s0; sh[1][wid] = s1; sh[2][wid] = s2; }
    __syncthreads();
    if (wid == 0) {
        s0 = (lane < 8) ? sh[0][lane] : 0.f;
        s1 = (lane < 8) ? sh[1][lane] : 0.f;
        s2 = (lane < 8) ? sh[2][lane] : 0.f;
        #pragma unroll
        for (int off = 4; off; off >>= 1) {
            s0 += __shfl_down_sync(0xffffffffu, s0, off);
            s1 += __shfl_down_sync(0xffffffffu, s1, off);
            s2 += __shfl_down_sync(0xffffffffu, s2, off);
        }
        if (lane == 0) {
            float* dst = &g_part[(b * PARTS + p) * 3];
            dst[0] = s0; dst[1] = s1; dst[2] = s2;
        }
    }
    pdl_launch_dependents();
}

// ---------------------------------------------------------------------------
// Kernel 2: finalize per-batch parameters.  One block, 256 threads.
// Partial loads front-batched (MLP=24) to shorten the inter-kernel path.
// ---------------------------------------------------------------------------
__global__ void finalize_kernel(const float* __restrict__ gaze)
{
    pdl_wait();    // all sal_reduce partials visible after this
    const int b    = threadIdx.x >> 3;        // 0..31
    const int part = threadIdx.x & 7;         // 0..7

    float buf[24];
    #pragma unroll
    for (int i = 0; i < 8; i++) {
        const float* src = &g_part[(b * PARTS + part * 8 + i) * 3];
        buf[i * 3 + 0] = __ldg(&src[0]);
        buf[i * 3 + 1] = __ldg(&src[1]);
        buf[i * 3 + 2] = __ldg(&src[2]);
    }
    float s0 = 0.f, s1 = 0.f, s2 = 0.f;
    #pragma unroll
    for (int i = 0; i < 8; i++) {
        s0 += buf[i * 3 + 0];
        s1 += buf[i * 3 + 1];
        s2 += buf[i * 3 + 2];
    }
    #pragma unroll
    for (int off = 4; off; off >>= 1) {
        s0 += __shfl_down_sync(0xffffffffu, s0, off);
        s1 += __shfl_down_sync(0xffffffffu, s1, off);
        s2 += __shfl_down_sync(0xffffffffu, s2, off);
    }
    if (part == 0) {
        const float xg = __ldg(&gaze[2 * b]);
        const float yg = __ldg(&gaze[2 * b + 1]);
        float inv = 1.0f / (s0 + 1e-6f);
        float mean_r  = s1 * inv;
        float mean_r2 = s2 * inv;
        float var = mean_r2 - mean_r * mean_r;
        float std_r = sqrtf(fmaxf(var, 0.0f));
        // r_max attained at an image corner (r monotone in |dx|,|dy|)
        float mdx = fmaxf(xg, 511.0f - xg);
        float mdy = fmaxf(yg, 511.0f - yg);
        float r_max = sqrtf(mdx * mdx + mdy * mdy + 1e-6f);
        float fe = FOV * (1.0f + 0.5f * (std_r / r_max));
        // max r_tfm = peri(r_max)  (monotone, r_max > fe always)
        float denom = 2.0f * (fe + KCONST);
        float addc  = (fe - KCONST) * 0.5f;
        float t = r_max + KCONST;
        float rtfm_max = t * t / denom + addc;
        float coef = r_max / (rtfm_max + 1e-6f);
        float4* prm4 = (float4*)&g_params[b * 8];
        prm4[0] = make_float4(xg, yg, fe, coef);
        prm4[1] = make_float4(1.0f / denom, addc, 0.f, 0.f);
    }
    pdl_launch_dependents();
}

// ---------------------------------------------------------------------------
// Kernel 3: warp + bilinear + quantize.  One block = one (batch,row).
// Each of 256 threads handles pixels x and x+256 (lane stride 1).
// Pre-pdl_wait: L2 prefetch of this block's img row (runs concurrently with
// sal_reduce drain under PDL; no register dependencies, no replay cost).
// Geometry proofs (R7/R8): no masks, no clamps; normalize round-trip skipped.
// ---------------------------------------------------------------------------
__global__ void __launch_bounds__(256) warp_sample_kernel(
    const float* __restrict__ img, float* __restrict__ out)
{
    const int b = blockIdx.x >> 9;
    const int y = blockIdx.x & 511;
    const float* imb = img + (size_t)b * 3 * NHW;

    // ---- pre-wait L2 warm-up: prefetch this output row's img rows ----
    // (source band is near the identity row; collectively the grid touches
    //  all of img, warming L2 before any gather executes)
    {
        const float* row = imb + y * NW + threadIdx.x * 2;
        prefetch_l2(row);
        prefetch_l2(row + NHW);
        prefetch_l2(row + 2 * NHW);
    }

    pdl_wait();    // params visible after this

    const float4 p0 = __ldg((const float4*)&g_params[b * 8]);
    const float2 p1 = __ldg((const float2*)&g_params[b * 8 + 4]);
    const float xg     = p0.x;
    const float yg     = p0.y;
    const float fe     = p0.z;
    const float coef   = p0.w;
    const float invden = p1.x;
    const float addc   = p1.y;

    const float dy  = (float)y - yg;
    const float dy2 = fmaf(dy, dy, 1e-6f);
    float* outb = out + (size_t)b * 3 * NHW + y * NW;

    int   oo[2];
    float mm[2][4];

    #pragma unroll
    for (int p = 0; p < 2; p++) {
        const int x = threadIdx.x + p * 256;
        float dx = (float)x - xg;
        float d2 = fmaf(dx, dx, dy2);
        float invr = rsqrtf(d2);
        float r    = d2 * invr;

        float t  = r + KCONST;
        float rp = fmaf(t * t, invden, addc);
        float rt = (r < fe) ? r : rp;
        float s  = coef * rt * invr;          // rn / r
        float fx = fmaf(dx, s, xg);           // in [0,511] +- 1e-5
        float fy = fmaf(dy, s, yg);

        int x0i = min((int)fx, 510);          // trunc == floor (fx >= -1e-5)
        int y0i = min((int)fy, 510);
        float wx1 = fx - (float)x0i;
        float wy1 = fy - (float)y0i;
        float wx0 = 1.0f - wx1;
        float wy0 = 1.0f - wy1;

        mm[p][0] = wy0 * wx0;
        mm[p][1] = wy0 * wx1;
        mm[p][2] = wy1 * wx0;
        mm[p][3] = wy1 * wx1;
        oo[p] = y0i * NW + x0i;               // +1, +512, +513 all in-bounds
    }

    // front-batch all 24 gather loads (addresses: 1 IMAD + imm offsets)
    float g[2][12];
    #pragma unroll
    for (int p = 0; p < 2; p++) {
        #pragma unroll
        for (int c = 0; c < 3; c++) {
            const float* ic = imb + (size_t)c * NHW + oo[p];
            g[p][c * 4 + 0] = __ldg(ic);
            g[p][c * 4 + 1] = __ldg(ic + 1);
            g[p][c * 4 + 2] = __ldg(ic + NW);
            g[p][c * 4 + 3] = __ldg(ic + NW + 1);
        }
    }

    #pragma unroll
    for (int p = 0; p < 2; p++) {
        #pragma unroll
        for (int c = 0; c < 3; c++) {
            float v = g[p][c * 4 + 0] * mm[p][0] + g[p][c * 4 + 1] * mm[p][1] +
                      g[p][c * 4 + 2] * mm[p][2] + g[p][c * 4 + 3] * mm[p][3];
            // v is a convex combo of [0,255] values: no clamp needed.
            // u8 quantization (trunc, matches XLA), stored f32, streaming.
            __stcs(outb + (size_t)c * NHW + threadIdx.x + p * 256, truncf(v));
        }
    }
}

// ---------------------------------------------------------------------------
extern "C" void kernel_launch(void* const* d_in, const int* in_sizes, int n_in,
                              void* d_out, int out_size)
{
    const float* img  = (const float*)d_in[0];
    const float* gaze = (const float*)d_in[1];
    const float* sal  = (const float*)d_in[2];
    float* out = (float*)d_out;

    dim3 g1(PARTS, NB);
    sal_reduce_kernel<<<g1, 256>>>(sal, gaze);

    // finalize: PDL secondary (overlaps sal_reduce drain)
    {
        cudaLaunchConfig_t cfg = {};
        cudaLaunchAttribute attr[1];
        attr[0].id = cudaLaunchAttributeProgrammaticStreamSerialization;
        attr[0].val.programmaticStreamSerializationAllowed = 1;
        cfg.gridDim = dim3(1, 1, 1);
        cfg.blockDim = dim3(256, 1, 1);
        cfg.attrs = attr;
        cfg.numAttrs = 1;
        cudaLaunchKernelEx(&cfg, finalize_kernel, gaze);
    }

    // warp_sample: PDL secondary (overlaps finalize drain)
    {
        cudaLaunchConfig_t cfg = {};
        cudaLaunchAttribute attr[1];
        attr[0].id = cudaLaunchAttributeProgrammaticStreamSerialization;
        attr[0].val.programmaticStreamSerializationAllowed = 1;
        cfg.gridDim = dim3(NB * NH, 1, 1);
        cfg.blockDim = dim3(256, 1, 1);
        cfg.attrs = attr;
        cfg.numAttrs = 1;
        cudaLaunchKernelEx(&cfg, warp_sample_kernel, img, out);
    }
}

// round 16
// speedup vs baseline: 1.0318x; 1.0318x over previous
#include <cuda_runtime.h>
#include <cstdint>

#define NB 32
#define NH 512
#define NW 512
#define NHW (NH * NW)          // 262144
#define PARTS 64
#define CHUNK (NHW / PARTS)    // 4096
#define FOV 160.0f             // 0.3125 * 512
#define KCONST 106.496f        // 0.208  * 512

// scratch (no allocations allowed)
__device__ float g_part[NB * PARTS * 3];
__device__ float g_params[NB * 8];   // xg, yg, fe, coef | invden, addc

// --- PDL helpers -----------------------------------------------------------
__device__ __forceinline__ void pdl_wait() {
    asm volatile("griddepcontrol.wait;" ::: "memory");
}
__device__ __forceinline__ void pdl_launch_dependents() {
    asm volatile("griddepcontrol.launch_dependents;" ::: "memory");
}

// ---------------------------------------------------------------------------
// Kernel 1: per-(batch, part) partial sums of S, S*r, S*r^2
// grid = (PARTS, NB) = 2048 blocks x 256. 4 front-batched LDG.128 (MLP=4).
// ---------------------------------------------------------------------------
__global__ void __launch_bounds__(256, 8) sal_reduce_kernel(
    const float* __restrict__ sal, const float* __restrict__ gaze)
{
    const int b = blockIdx.y;
    const int p = blockIdx.x;
    const float xg = __ldg(&gaze[2 * b]);
    const float yg = __ldg(&gaze[2 * b + 1]);
    const float4* S4 = (const float4*)(sal + (size_t)b * NHW + (size_t)p * CHUNK);
    const int base_lin = p * CHUNK;

    // front-batch all 4 LDG.128s for memory-level parallelism
    float4 v[4];
    #pragma unroll
    for (int it = 0; it < 4; it++)
        v[it] = __ldg(&S4[it * 256 + threadIdx.x]);

    float s0 = 0.f, s1 = 0.f, s2 = 0.f;
    #pragma unroll
    for (int it = 0; it < 4; it++) {
        int lin = base_lin + (it * 256 + threadIdx.x) * 4;
        float dy = (float)(lin >> 9) - yg;
        float dy2 = fmaf(dy, dy, 1e-6f);
        int x0 = lin & 511;
        #pragma unroll
        for (int k = 0; k < 4; k++) {
            float dx = (float)(x0 + k) - xg;
            float d2 = fmaf(dx, dx, dy2);
            float r  = d2 * rsqrtf(d2);       // r = sqrt(d2), 1 MUFU
            float sv = (&v[it].x)[k];
            s0 += sv;
            s1 = fmaf(sv, r, s1);
            s2 = fmaf(sv, d2, s2);            // r^2 == d2 exactly
        }
    }

    // block reduction
    __shared__ float sh[3][8];
    #pragma unroll
    for (int off = 16; off; off >>= 1) {
        s0 += __shfl_down_sync(0xffffffffu, s0, off);
        s1 += __shfl_down_sync(0xffffffffu, s1, off);
        s2 += __shfl_down_sync(0xffffffffu, s2, off);
    }
    const int wid = threadIdx.x >> 5, lane = threadIdx.x & 31;
    if (lane == 0) { sh[0][wid] = s0; sh[1][wid] = s1; sh[2][wid] = s2; }
    __syncthreads();
    if (wid == 0) {
        s0 = (lane < 8) ? sh[0][lane] : 0.f;
        s1 = (lane < 8) ? sh[1][lane] : 0.f;
        s2 = (lane < 8) ? sh[2][lane] : 0.f;
        #pragma unroll
        for (int off = 4; off; off >>= 1) {
            s0 += __shfl_down_sync(0xffffffffu, s0, off);
            s1 += __shfl_down_sync(0xffffffffu, s1, off);
            s2 += __shfl_down_sync(0xffffffffu, s2, off);
        }
        if (lane == 0) {
            float* dst = &g_part[(b * PARTS + p) * 3];
            dst[0] = s0; dst[1] = s1; dst[2] = s2;
        }
    }
    pdl_launch_dependents();
}

// ---------------------------------------------------------------------------
// Kernel 2: finalize per-batch parameters.  One block, 256 threads.
// Partial loads front-batched (MLP=24) to shorten the inter-kernel path.
// ---------------------------------------------------------------------------
__global__ void finalize_kernel(const float* __restrict__ gaze)
{
    pdl_wait();    // all sal_reduce partials visible after this
    const int b    = threadIdx.x >> 3;        // 0..31
    const int part = threadIdx.x & 7;         // 0..7

    float buf[24];
    #pragma unroll
    for (int i = 0; i < 8; i++) {
        const float* src = &g_part[(b * PARTS + part * 8 + i) * 3];
        buf[i * 3 + 0] = __ldg(&src[0]);
        buf[i * 3 + 1] = __ldg(&src[1]);
        buf[i * 3 + 2] = __ldg(&src[2]);
    }
    float s0 = 0.f, s1 = 0.f, s2 = 0.f;
    #pragma unroll
    for (int i = 0; i < 8; i++) {
        s0 += buf[i * 3 + 0];
        s1 += buf[i * 3 + 1];
        s2 += buf[i * 3 + 2];
    }
    #pragma unroll
    for (int off = 4; off; off >>= 1) {
        s0 += __shfl_down_sync(0xffffffffu, s0, off);
        s1 += __shfl_down_sync(0xffffffffu, s1, off);
        s2 += __shfl_down_sync(0xffffffffu, s2, off);
    }
    if (part == 0) {
        const float xg = __ldg(&gaze[2 * b]);
        const float yg = __ldg(&gaze[2 * b + 1]);
        float inv = 1.0f / (s0 + 1e-6f);
        float mean_r  = s1 * inv;
        float mean_r2 = s2 * inv;
        float var = mean_r2 - mean_r * mean_r;
        float std_r = sqrtf(fmaxf(var, 0.0f));
        // r_max attained at an image corner (r monotone in |dx|,|dy|)
        float mdx = fmaxf(xg, 511.0f - xg);
        float mdy = fmaxf(yg, 511.0f - yg);
        float r_max = sqrtf(mdx * mdx + mdy * mdy + 1e-6f);
        float fe = FOV * (1.0f + 0.5f * (std_r / r_max));
        // max r_tfm = peri(r_max)  (monotone, r_max > fe always)
        float denom = 2.0f * (fe + KCONST);
        float addc  = (fe - KCONST) * 0.5f;
        float t = r_max + KCONST;
        float rtfm_max = t * t / denom + addc;
        float coef = r_max / (rtfm_max + 1e-6f);
        float4* prm4 = (float4*)&g_params[b * 8];
        prm4[0] = make_float4(xg, yg, fe, coef);
        prm4[1] = make_float4(1.0f / denom, addc, 0.f, 0.f);
    }
    pdl_launch_dependents();
}

// ---------------------------------------------------------------------------
// Kernel 3: warp + bilinear + quantize.  One block = one (batch,row).
// Each of 256 threads handles pixels x and x+256 (lane stride 1).
// No shared memory, no barriers (43.7us measured in R9).
// Geometry proofs (R7/R8): no masks, no clamps; normalize round-trip skipped.
// ---------------------------------------------------------------------------
__global__ void __launch_bounds__(256) warp_sample_kernel(
    const float* __restrict__ img, float* __restrict__ out)
{
    pdl_wait();    // params visible after this

    const int b = blockIdx.x >> 9;
    const int y = blockIdx.x & 511;

    const float4 p0 = __ldg((const float4*)&g_params[b * 8]);
    const float2 p1 = __ldg((const float2*)&g_params[b * 8 + 4]);
    const float xg     = p0.x;
    const float yg     = p0.y;
    const float fe     = p0.z;
    const float coef   = p0.w;
    const float invden = p1.x;
    const float addc   = p1.y;

    const float dy  = (float)y - yg;
    const float dy2 = fmaf(dy, dy, 1e-6f);
    const float* imb = img + (size_t)b * 3 * NHW;
    float* outb = out + (size_t)b * 3 * NHW + y * NW;

    int   oo[2];
    float mm[2][4];

    #pragma unroll
    for (int p = 0; p < 2; p++) {
        const int x = threadIdx.x + p * 256;
        float dx = (float)x - xg;
        float d2 = fmaf(dx, dx, dy2);
        float invr = rsqrtf(d2);
        float r    = d2 * invr;

        float t  = r + KCONST;
        float rp = fmaf(t * t, invden, addc);
        float rt = (r < fe) ? r : rp;
        float s  = coef * rt * invr;          // rn / r
        float fx = fmaf(dx, s, xg);           // in [0,511] +- 1e-5
        float fy = fmaf(dy, s, yg);

        int x0i = min((int)fx, 510);          // trunc == floor (fx >= -1e-5)
        int y0i = min((int)fy, 510);
        float wx1 = fx - (float)x0i;
        float wy1 = fy - (float)y0i;
        float wx0 = 1.0f - wx1;
        float wy0 = 1.0f - wy1;

        mm[p][0] = wy0 * wx0;
        mm[p][1] = wy0 * wx1;
        mm[p][2] = wy1 * wx0;
        mm[p][3] = wy1 * wx1;
        oo[p] = y0i * NW + x0i;               // +1, +512, +513 all in-bounds
    }

    // front-batch all 24 gather loads (addresses: 1 IMAD + imm offsets)
    float g[2][12];
    #pragma unroll
    for (int p = 0; p < 2; p++) {
        #pragma unroll
        for (int c = 0; c < 3; c++) {
            const float* ic = imb + (size_t)c * NHW + oo[p];
            g[p][c * 4 + 0] = __ldg(ic);
            g[p][c * 4 + 1] = __ldg(ic + 1);
            g[p][c * 4 + 2] = __ldg(ic + NW);
            g[p][c * 4 + 3] = __ldg(ic + NW + 1);
        }
    }

    #pragma unroll
    for (int p = 0; p < 2; p++) {
        #pragma unroll
        for (int c = 0; c < 3; c++) {
            float v = g[p][c * 4 + 0] * mm[p][0] + g[p][c * 4 + 1] * mm[p][1] +
                      g[p][c * 4 + 2] * mm[p][2] + g[p][c * 4 + 3] * mm[p][3];
            // v is a convex combo of [0,255] values: no clamp needed.
            // u8 quantization (trunc, matches XLA), stored f32, streaming.
            __stcs(outb + (size_t)c * NHW + threadIdx.x + p * 256, truncf(v));
        }
    }
}

// ---------------------------------------------------------------------------
extern "C" void kernel_launch(void* const* d_in, const int* in_sizes, int n_in,
                              void* d_out, int out_size)
{
    const float* img  = (const float*)d_in[0];
    const float* gaze = (const float*)d_in[1];
    const float* sal  = (const float*)d_in[2];
    float* out = (float*)d_out;

    dim3 g1(PARTS, NB);
    sal_reduce_kernel<<<g1, 256>>>(sal, gaze);

    // finalize: PDL secondary (overlaps sal_reduce drain)
    {
        cudaLaunchConfig_t cfg = {};
        cudaLaunchAttribute attr[1];
        attr[0].id = cudaLaunchAttributeProgrammaticStreamSerialization;
        attr[0].val.programmaticStreamSerializationAllowed = 1;
        cfg.gridDim = dim3(1, 1, 1);
        cfg.blockDim = dim3(256, 1, 1);
        cfg.attrs = attr;
        cfg.numAttrs = 1;
        cudaLaunchKernelEx(&cfg, finalize_kernel, gaze);
    }

    // warp_sample: PDL secondary (overlaps finalize drain)
    {
        cudaLaunchConfig_t cfg = {};
        cudaLaunchAttribute attr[1];
        attr[0].id = cudaLaunchAttributeProgrammaticStreamSerialization;
        attr[0].val.programmaticStreamSerializationAllowed = 1;
        cfg.gridDim = dim3(NB * NH, 1, 1);
        cfg.blockDim = dim3(256, 1, 1);
        cfg.attrs = attr;
        cfg.numAttrs = 1;
        cudaLaunchKernelEx(&cfg, warp_sample_kernel, img, out);
    }
}